// round 7
// baseline (speedup 1.0000x reference)
#include <cuda_runtime.h>
#include <math.h>

#define BATCH  2
#define NHEADS 16
#define BH     32
#define SQ     2048
#define SK     4096
#define DH     64
#define QT     64
#define KTILE  64
#define LS     68          // Q/K smem row stride (floats)
#define PS     72          // P smem row stride (floats): banks 8ty+tx, conflict-free
#define VHS    36          // V half-row stride
// smem word offsets
#define QOFF   0
#define KOFF   4352                   // Q: 64*68
#define KBUF   4352                   // per K buffer
#define VOFF   (KOFF + 2*KBUF)        // 13056
#define VBUF   4640                   // 2*(64*36) + 32 pad; halves offset 2308 (+4 banks)
#define VHALF  2308
#define POFF   (VOFF + 2*VBUF)        // 22336
#define SMWORDS (POFF + QT*PS)        // 26944 words = 107776 B

typedef unsigned long long ull;

__device__ __forceinline__ ull pk2(float lo, float hi) {
    ull r; asm("mov.b64 %0,{%1,%2};" : "=l"(r) : "f"(lo), "f"(hi)); return r;
}
__device__ __forceinline__ void upk2(ull v, float& lo, float& hi) {
    asm("mov.b64 {%0,%1},%2;" : "=f"(lo), "=f"(hi) : "l"(v));
}
__device__ __forceinline__ ull ffma2(ull a, ull b, ull c) {
    ull d; asm("fma.rn.f32x2 %0,%1,%2,%3;" : "=l"(d) : "l"(a), "l"(b), "l"(c)); return d;
}
__device__ __forceinline__ ull fmul2(ull a, ull b) {
    ull d; asm("mul.rn.f32x2 %0,%1,%2;" : "=l"(d) : "l"(a), "l"(b)); return d;
}
__device__ __forceinline__ void cpa16(unsigned int dst, const void* src) {
    asm volatile("cp.async.cg.shared.global [%0], [%1], 16;" :: "r"(dst), "l"(src));
}

// ---------------- scratch ----------------
__device__ int   g_posq[BATCH * SQ];
__device__ float g_cosT[SK * 16];
__device__ float g_sinT[SK * 16];
__device__ float g_qr[BH * SQ * DH];
__device__ float g_kr[BH * SK * DH];

// ---------------- kernel 1: gather query positions -------------------------
__global__ void build_idx_kernel(const void* candA, const void* candB) {
    __shared__ int warp_sums[32];
    const int b   = blockIdx.x;
    const int tid = threadIdx.x;          // 1024 threads

    const int*   ai = (const int*)candA;  const float* af = (const float*)candA;
    const int*   bi = (const int*)candB;  const float* bf = (const float*)candB;
    bool a_is_pos = (ai[1] == 1 && ai[2] == 2 && ai[3] == 3 && ai[100] == 100) ||
                    (af[1] == 1.0f && af[2] == 2.0f && af[3] == 3.0f && af[100] == 100.0f);
    bool b_is_pos = (bi[1] == 1 && bi[2] == 2 && bi[3] == 3 && bi[100] == 100) ||
                    (bf[1] == 1.0f && bf[2] == 2.0f && bf[3] == 3.0f && bf[100] == 100.0f);
    const void* skipv = a_is_pos ? candB : (b_is_pos ? candA : candB);

    const unsigned int* sw = (const unsigned int*)skipv;
    bool w4 = true;
#pragma unroll
    for (int i = 0; i < 32; i++) {
        unsigned int x = sw[i];
        w4 = w4 && (x <= 1u || x == 0x3f800000u);
    }
    const unsigned char* s8  = (const unsigned char*)skipv;
    const unsigned int*  s32 = (const unsigned int*)skipv;

    g_posq[b * SQ + tid * 2]     = 0;
    g_posq[b * SQ + tid * 2 + 1] = 0;
    __syncthreads();

    const int base = tid * 4;
    int flags[4]; int c = 0;
#pragma unroll
    for (int u = 0; u < 4; u++) {
        int idx = b * SK + base + u;
        flags[u] = (w4 ? (s32[idx] != 0u) : (s8[idx] != 0)) ? 1 : 0;
        c += flags[u];
    }
    const int lane = tid & 31, warp = tid >> 5;
    int pre = c;
#pragma unroll
    for (int o = 1; o < 32; o <<= 1) {
        int t = __shfl_up_sync(0xffffffffu, pre, o);
        if (lane >= o) pre += t;
    }
    if (lane == 31) warp_sums[warp] = pre;
    __syncthreads();
    if (warp == 0) {
        int s = warp_sums[lane];
#pragma unroll
        for (int o = 1; o < 32; o <<= 1) {
            int t = __shfl_up_sync(0xffffffffu, s, o);
            if (lane >= o) s += t;
        }
        warp_sums[lane] = s;
    }
    __syncthreads();
    int offset = pre - c + (warp ? warp_sums[warp - 1] : 0);
#pragma unroll
    for (int u = 0; u < 4; u++) {
        if (flags[u] && offset < SQ)
            g_posq[b * SQ + offset] = base + u;
        offset += flags[u];
    }
}

// ---------------- kernel 2: cos/sin table ----------------------------------
__global__ void build_tab_kernel() {
    int i = blockIdx.x * blockDim.x + threadIdx.x;
    if (i >= SK * 16) return;
    int p = i >> 4, f = i & 15;
    float invf = (float)(1.0 / pow(10000.0, (double)(2 * f) / 32.0));
    float ang  = (float)p * invf;
    g_cosT[i] = cosf(ang);
    g_sinT[i] = sinf(ang);
}

// ---------------- kernel 3: RoPE on Q (scaled) ------------------------------
__global__ void rope_q_kernel(const float* __restrict__ q) {
    int t = blockIdx.x * blockDim.x + threadIdx.x;
    if (t >= BH * SQ * 32) return;
    int u   = t & 31;
    int row = t >> 5;
    int b   = row / (NHEADS * SQ);
    int r   = row & (SQ - 1);
    const float* x = q    + (size_t)row * DH;
    float*       y = g_qr + (size_t)row * DH;
    const float sc = 0.125f;
    if (u < 16) {
        int pos = g_posq[b * SQ + r];
        pos = min(max(pos, 0), SK - 1);
        float c  = g_cosT[pos * 16 + u];
        float s2 = g_sinT[pos * 16 + u];
        float x1 = x[u], x2 = x[u + 16];
        y[u]      = (x1 * c - x2 * s2) * sc;
        y[u + 16] = (x2 * c + x1 * s2) * sc;
    } else {
        int d = u + 16;
        y[d]      = x[d] * sc;
        y[d + 16] = x[d + 16] * sc;
    }
}

// ---------------- kernel 4: RoPE on K ---------------------------------------
__global__ void rope_k_kernel(const float* __restrict__ k) {
    int t = blockIdx.x * blockDim.x + threadIdx.x;
    if (t >= BH * SK * 32) return;
    int u   = t & 31;
    int row = t >> 5;
    int r   = row & (SK - 1);
    const float* x = k    + (size_t)row * DH;
    float*       y = g_kr + (size_t)row * DH;
    if (u < 16) {
        float c  = g_cosT[r * 16 + u];
        float s2 = g_sinT[r * 16 + u];
        float x1 = x[u], x2 = x[u + 16];
        y[u]      = x1 * c - x2 * s2;
        y[u + 16] = x2 * c + x1 * s2;
    } else {
        int d = u + 16;
        y[d]      = x[d];
        y[d + 16] = x[d + 16];
    }
}

// ---------------- kernel 5: flash attention ---------------------------------
// 256 threads, 64q x 64k tile, microtile 2q x 8k / 2q x 8d.
// cp.async double-buffered K/V; separate P buffer; 2 syncs per tile.
__global__ __launch_bounds__(256, 2)
void attn_kernel(const float* __restrict__ v, float* __restrict__ out) {
    extern __shared__ float sm[];
    float* qs = sm + QOFF;
    float* ps = sm + POFF;

    const int bh  = blockIdx.y;
    const int qt  = (int)gridDim.x - 1 - (int)blockIdx.x;   // heavy-first
    const int b   = bh >> 4;
    const int q0  = qt * QT;
    const int tid = threadIdx.x;
    const int tx  = tid & 7;
    const int ty  = tid >> 3;            // 0..31

    const float* qr = g_qr + ((size_t)bh * SQ + q0) * DH;
    const float* kr = g_kr + (size_t)bh * SK * DH;
    const float* vp = v    + (size_t)bh * SK * DH;

    const int pmax = g_posq[b * SQ + q0 + QT - 1];
    const int pmin = g_posq[b * SQ + q0];
    const int nkt  = pmax / KTILE + 1;
    int p[2];
    p[0] = g_posq[b * SQ + q0 + ty];
    p[1] = g_posq[b * SQ + q0 + ty + 32];

    // cp.async K/V tile loader: 1024 16B-chunks per tile (K) + 1024 (V), 8/thread
    const unsigned int smbase = (unsigned int)__cvta_generic_to_shared(sm);
    const int cr = tid >> 2;             // 0..63 : row handled by this thread
    const int cc = (tid & 3) * 4;        // chunk col group: 4 consecutive chunks

    // issue tile 0 copies
    {
        const int k0 = 0;
        unsigned int kb = smbase + (KOFF) * 4;
        unsigned int vb = smbase + (VOFF) * 4;
#pragma unroll
        for (int u = 0; u < 4; u++) {
            int c = cc + u;              // 0..15
            cpa16(kb + (cr * LS + c * 4) * 4, kr + (size_t)(k0 + cr) * DH + c * 4);
            unsigned int vdst = (c < 8)
                ? vb + (cr * VHS + c * 4) * 4
                : vb + (VHALF + cr * VHS + (c - 8) * 4) * 4;
            cpa16(vdst, vp + (size_t)(k0 + cr) * DH + c * 4);
        }
        asm volatile("cp.async.commit_group;");
    }

    // load Q tile (plain LDG/STS, covered by first sync)
#pragma unroll
    for (int i = 0; i < 4; i++) {
        int fid = tid + i * 256;
        int r = fid >> 4, c = (fid & 15) * 4;
        float4 f = *(const float4*)(qr + r * DH + c);
        *(float4*)(qs + r * LS + c) = f;
    }

    float m[2], l[2];
    ull o2[2][4];
#pragma unroll
    for (int i = 0; i < 2; i++) {
        m[i] = -1e30f; l[i] = 0.f;
#pragma unroll
        for (int j = 0; j < 4; j++) o2[i][j] = 0ULL;
    }

    const float* qrow0 = qs + ty * LS;
    const float* qrow1 = qs + (ty + 32) * LS;

    for (int t = 0; t < nkt; t++) {
        const int bsel = t & 1;
        const float* ks = sm + KOFF + bsel * KBUF;
        const float* vsb = sm + VOFF + bsel * VBUF;

        asm volatile("cp.async.wait_group 0;");
        __syncthreads();                 // tile t visible; PV(t-1) + P reads done

        // prefetch tile t+1
        if (t + 1 < nkt) {
            const int k0n = (t + 1) * KTILE;
            unsigned int kb = smbase + (KOFF + ((t + 1) & 1) * KBUF) * 4;
            unsigned int vb = smbase + (VOFF + ((t + 1) & 1) * VBUF) * 4;
#pragma unroll
            for (int u = 0; u < 4; u++) {
                int c = cc + u;
                cpa16(kb + (cr * LS + c * 4) * 4, kr + (size_t)(k0n + cr) * DH + c * 4);
                unsigned int vdst = (c < 8)
                    ? vb + (cr * VHS + c * 4) * 4
                    : vb + (VHALF + cr * VHS + (c - 8) * 4) * 4;
                cpa16(vdst, vp + (size_t)(k0n + cr) * DH + c * 4);
            }
        }
        asm volatile("cp.async.commit_group;");

        // ---- S = Q K^T (packed over reduction dim) ----
        ull s2[2][8];
#pragma unroll
        for (int i = 0; i < 2; i++)
#pragma unroll
            for (int j = 0; j < 8; j++) s2[i][j] = 0ULL;

#pragma unroll
        for (int kk = 0; kk < DH; kk += 4) {
            ulonglong2 a0 = *(const ulonglong2*)(qrow0 + kk);
            ulonglong2 a1 = *(const ulonglong2*)(qrow1 + kk);
            ulonglong2 b4[8];
#pragma unroll
            for (int j = 0; j < 8; j++)
                b4[j] = *(const ulonglong2*)(ks + (tx + 8 * j) * LS + kk);
#pragma unroll
            for (int j = 0; j < 8; j++) {
                s2[0][j] = ffma2(a0.x, b4[j].x, s2[0][j]);
                s2[0][j] = ffma2(a0.y, b4[j].y, s2[0][j]);
                s2[1][j] = ffma2(a1.x, b4[j].x, s2[1][j]);
                s2[1][j] = ffma2(a1.y, b4[j].y, s2[1][j]);
            }
        }

        float s[2][8];
        const int k0 = t * KTILE;
#pragma unroll
        for (int i = 0; i < 2; i++)
#pragma unroll
            for (int j = 0; j < 8; j++) {
                float lo, hi; upk2(s2[i][j], lo, hi);
                s[i][j] = lo + hi;
            }

        if (k0 + KTILE - 1 > pmin) {
#pragma unroll
            for (int i = 0; i < 2; i++)
#pragma unroll
                for (int j = 0; j < 8; j++)
                    if (k0 + tx + 8 * j > p[i]) s[i][j] = -1e30f;
        }

        // online softmax (rows reduced over 8 consecutive lanes)
        float fac[2];
#pragma unroll
        for (int i = 0; i < 2; i++) {
            float mt = s[i][0];
#pragma unroll
            for (int j = 1; j < 8; j++) mt = fmaxf(mt, s[i][j]);
            mt = fmaxf(mt, __shfl_xor_sync(0xffffffffu, mt, 1));
            mt = fmaxf(mt, __shfl_xor_sync(0xffffffffu, mt, 2));
            mt = fmaxf(mt, __shfl_xor_sync(0xffffffffu, mt, 4));
            float mn = fmaxf(m[i], mt);
            fac[i] = __expf(m[i] - mn);
            m[i] = mn;
            float rs = 0.f;
#pragma unroll
            for (int j = 0; j < 8; j++) { s[i][j] = __expf(s[i][j] - mn); rs += s[i][j]; }
            rs += __shfl_xor_sync(0xffffffffu, rs, 1);
            rs += __shfl_xor_sync(0xffffffffu, rs, 2);
            rs += __shfl_xor_sync(0xffffffffu, rs, 4);
            l[i] = l[i] * fac[i] + rs;
            ull f2 = pk2(fac[i], fac[i]);
#pragma unroll
            for (int j = 0; j < 4; j++) o2[i][j] = fmul2(o2[i][j], f2);
        }

        // stage P (separate buffer, stride 72: banks 8ty+tx conflict-free)
#pragma unroll
        for (int i = 0; i < 2; i++)
#pragma unroll
            for (int j = 0; j < 8; j++)
                ps[(ty + 32 * i) * PS + tx + 8 * j] = s[i][j];
        __syncthreads();

        // ---- O += P V (packed over output dims; V in conflict-free halves) ----
        const float* va = vsb + (tx < 4 ? tx * 8 : VHALF + (tx - 4) * 8);
#pragma unroll
        for (int kk = 0; kk < KTILE; kk += 4) {
            float4 pa0 = *(const float4*)(ps + ty * PS + kk);
            float4 pa1 = *(const float4*)(ps + (ty + 32) * PS + kk);
#pragma unroll
            for (int u = 0; u < 4; u++) {
                const float* vr = va + (kk + u) * VHS;
                ulonglong2 vv = *(const ulonglong2*)(vr);
                float p0 = ((const float*)&pa0)[u];
                float p1 = ((const float*)&pa1)[u];
                ull pr0 = pk2(p0, p0);
                ull pr1 = pk2(p1, p1);
                o2[0][0] = ffma2(pr0, vv.x, o2[0][0]);
                o2[0][1] = ffma2(pr0, vv.y, o2[0][1]);
                o2[1][0] = ffma2(pr1, vv.x, o2[1][0]);
                o2[1][1] = ffma2(pr1, vv.y, o2[1][1]);
                ulonglong2 vw = *(const ulonglong2*)(vr + 4);
                o2[0][2] = ffma2(pr0, vw.x, o2[0][2]);
                o2[0][3] = ffma2(pr0, vw.y, o2[0][3]);
                o2[1][2] = ffma2(pr1, vw.x, o2[1][2]);
                o2[1][3] = ffma2(pr1, vw.y, o2[1][3]);
            }
        }
    }

    // epilogue
#pragma unroll
    for (int i = 0; i < 2; i++) {
        float inv = 1.0f / l[i];
        ull iv = pk2(inv, inv);
        ulonglong2 w0, w1;
        w0.x = fmul2(o2[i][0], iv); w0.y = fmul2(o2[i][1], iv);
        w1.x = fmul2(o2[i][2], iv); w1.y = fmul2(o2[i][3], iv);
        float* orow = out + ((size_t)bh * SQ + q0 + ty + 32 * i) * DH + tx * 8;
        *(ulonglong2*)orow       = w0;
        *(ulonglong2*)(orow + 4) = w1;
    }
}

// ---------------- launch ------------------------------------------------------
extern "C" void kernel_launch(void* const* d_in, const int* in_sizes, int n_in,
                              void* d_out, int out_size) {
    const float* q = nullptr; const float* k = nullptr; const float* v = nullptr;
    const void* cand[2] = {nullptr, nullptr}; int nc = 0;
    for (int i = 0; i < n_in; i++) {
        long long sz = in_sizes[i];
        if (sz == 4194304) { q = (const float*)d_in[i]; }
        else if (sz == 8388608) { if (!k) k = (const float*)d_in[i]; else v = (const float*)d_in[i]; }
        else if (sz == 8192) { if (nc < 2) cand[nc++] = d_in[i]; }
    }
    if (nc == 1) cand[1] = cand[0];
    if (!q || !k || !v || nc == 0) {
        q = (const float*)d_in[0]; k = (const float*)d_in[1]; v = (const float*)d_in[2];
        cand[0] = d_in[4]; cand[1] = d_in[5];
    }
    float* out = (float*)d_out;

    build_idx_kernel<<<BATCH, 1024>>>(cand[0], cand[1]);
    build_tab_kernel<<<(SK * 16 + 255) / 256, 256>>>();
    rope_q_kernel<<<(BH * SQ * 32 + 255) / 256, 256>>>(q);
    rope_k_kernel<<<(BH * SK * 32 + 255) / 256, 256>>>(k);

    const int smem_bytes = SMWORDS * (int)sizeof(float);   // 107776
    cudaFuncSetAttribute(attn_kernel,
                         cudaFuncAttributeMaxDynamicSharedMemorySize, smem_bytes);
    dim3 grid(SQ / QT, BH);
    attn_kernel<<<grid, 256, smem_bytes>>>(v, out);
}

// round 8
// speedup vs baseline: 1.3366x; 1.3366x over previous
#include <cuda_runtime.h>
#include <math.h>

#define BATCH  2
#define NHEADS 16
#define BH     32
#define SQ     2048
#define SK     4096
#define DH     64
#define QT     64
#define KTILE  64
#define LS     68          // Q/K smem row stride (floats)
#define PS     72          // P smem row stride: banks 8ty+tx, conflict-free
#define VHS    36          // V half-row stride
// smem word offsets
#define QOFF   0
#define KOFF   4352                   // Q: 64*68
#define KBUF   4352                   // per K buffer
#define VOFF   (KOFF + 2*KBUF)        // 13056
#define VBUF   4640                   // two 64x36 halves + pad; half1 at +2308 (+4 banks)
#define VHALF  2308
#define POFF   (VOFF + 2*VBUF)        // 22336
#define SMWORDS (POFF + QT*PS)        // 26944 words = 107776 B

typedef unsigned long long ull;

__device__ __forceinline__ ull pk2(float lo, float hi) {
    ull r; asm("mov.b64 %0,{%1,%2};" : "=l"(r) : "f"(lo), "f"(hi)); return r;
}
__device__ __forceinline__ void upk2(ull v, float& lo, float& hi) {
    asm("mov.b64 {%0,%1},%2;" : "=f"(lo), "=f"(hi) : "l"(v));
}
__device__ __forceinline__ ull ffma2(ull a, ull b, ull c) {
    ull d; asm("fma.rn.f32x2 %0,%1,%2,%3;" : "=l"(d) : "l"(a), "l"(b), "l"(c)); return d;
}
__device__ __forceinline__ ull fmul2(ull a, ull b) {
    ull d; asm("mul.rn.f32x2 %0,%1,%2;" : "=l"(d) : "l"(a), "l"(b)); return d;
}
__device__ __forceinline__ void cpa16(unsigned int dst, const void* src) {
    asm volatile("cp.async.cg.shared.global [%0], [%1], 16;" :: "r"(dst), "l"(src));
}

// ---------------- scratch ----------------
__device__ int   g_posq[BATCH * SQ];
__device__ float g_cosT[SK * 16];
__device__ float g_sinT[SK * 16];
__device__ float g_qr[BH * SQ * DH];
__device__ float g_kr[BH * SK * DH];

// ---------------- kernel 1: gather query positions -------------------------
__global__ void build_idx_kernel(const void* candA, const void* candB) {
    __shared__ int warp_sums[32];
    const int b   = blockIdx.x;
    const int tid = threadIdx.x;          // 1024 threads

    const int*   ai = (const int*)candA;  const float* af = (const float*)candA;
    const int*   bi = (const int*)candB;  const float* bf = (const float*)candB;
    bool a_is_pos = (ai[1] == 1 && ai[2] == 2 && ai[3] == 3 && ai[100] == 100) ||
                    (af[1] == 1.0f && af[2] == 2.0f && af[3] == 3.0f && af[100] == 100.0f);
    bool b_is_pos = (bi[1] == 1 && bi[2] == 2 && bi[3] == 3 && bi[100] == 100) ||
                    (bf[1] == 1.0f && bf[2] == 2.0f && bf[3] == 3.0f && bf[100] == 100.0f);
    const void* skipv = a_is_pos ? candB : (b_is_pos ? candA : candB);

    const unsigned int* sw = (const unsigned int*)skipv;
    bool w4 = true;
#pragma unroll
    for (int i = 0; i < 32; i++) {
        unsigned int x = sw[i];
        w4 = w4 && (x <= 1u || x == 0x3f800000u);
    }
    const unsigned char* s8  = (const unsigned char*)skipv;
    const unsigned int*  s32 = (const unsigned int*)skipv;

    g_posq[b * SQ + tid * 2]     = 0;
    g_posq[b * SQ + tid * 2 + 1] = 0;
    __syncthreads();

    const int base = tid * 4;
    int flags[4]; int c = 0;
#pragma unroll
    for (int u = 0; u < 4; u++) {
        int idx = b * SK + base + u;
        flags[u] = (w4 ? (s32[idx] != 0u) : (s8[idx] != 0)) ? 1 : 0;
        c += flags[u];
    }
    const int lane = tid & 31, warp = tid >> 5;
    int pre = c;
#pragma unroll
    for (int o = 1; o < 32; o <<= 1) {
        int t = __shfl_up_sync(0xffffffffu, pre, o);
        if (lane >= o) pre += t;
    }
    if (lane == 31) warp_sums[warp] = pre;
    __syncthreads();
    if (warp == 0) {
        int s = warp_sums[lane];
#pragma unroll
        for (int o = 1; o < 32; o <<= 1) {
            int t = __shfl_up_sync(0xffffffffu, s, o);
            if (lane >= o) s += t;
        }
        warp_sums[lane] = s;
    }
    __syncthreads();
    int offset = pre - c + (warp ? warp_sums[warp - 1] : 0);
#pragma unroll
    for (int u = 0; u < 4; u++) {
        if (flags[u] && offset < SQ)
            g_posq[b * SQ + offset] = base + u;
        offset += flags[u];
    }
}

// ---------------- kernel 2: cos/sin table ----------------------------------
__global__ void build_tab_kernel() {
    int i = blockIdx.x * blockDim.x + threadIdx.x;
    if (i >= SK * 16) return;
    int p = i >> 4, f = i & 15;
    float invf = (float)(1.0 / pow(10000.0, (double)(2 * f) / 32.0));
    float ang  = (float)p * invf;
    g_cosT[i] = cosf(ang);
    g_sinT[i] = sinf(ang);
}

// ---------------- kernel 3: RoPE on Q (scaled) ------------------------------
__global__ void rope_q_kernel(const float* __restrict__ q) {
    int t = blockIdx.x * blockDim.x + threadIdx.x;
    if (t >= BH * SQ * 32) return;
    int u   = t & 31;
    int row = t >> 5;
    int b   = row / (NHEADS * SQ);
    int r   = row & (SQ - 1);
    const float* x = q    + (size_t)row * DH;
    float*       y = g_qr + (size_t)row * DH;
    const float sc = 0.125f;
    if (u < 16) {
        int pos = g_posq[b * SQ + r];
        pos = min(max(pos, 0), SK - 1);
        float c  = g_cosT[pos * 16 + u];
        float s2 = g_sinT[pos * 16 + u];
        float x1 = x[u], x2 = x[u + 16];
        y[u]      = (x1 * c - x2 * s2) * sc;
        y[u + 16] = (x2 * c + x1 * s2) * sc;
    } else {
        int d = u + 16;
        y[d]      = x[d] * sc;
        y[d + 16] = x[d + 16] * sc;
    }
}

// ---------------- kernel 4: RoPE on K ---------------------------------------
__global__ void rope_k_kernel(const float* __restrict__ k) {
    int t = blockIdx.x * blockDim.x + threadIdx.x;
    if (t >= BH * SK * 32) return;
    int u   = t & 31;
    int row = t >> 5;
    int r   = row & (SK - 1);
    const float* x = k    + (size_t)row * DH;
    float*       y = g_kr + (size_t)row * DH;
    if (u < 16) {
        float c  = g_cosT[r * 16 + u];
        float s2 = g_sinT[r * 16 + u];
        float x1 = x[u], x2 = x[u + 16];
        y[u]      = x1 * c - x2 * s2;
        y[u + 16] = x2 * c + x1 * s2;
    } else {
        int d = u + 16;
        y[d]      = x[d];
        y[d + 16] = x[d + 16];
    }
}

// ---------------- kernel 5: flash attention ---------------------------------
// 128 threads, 64q x 64k tile, microtile 4q x 8k / 4q x 8d (R6 shape).
// cp.async double-buffered K/V; separate P buffer; 2 syncs/tile; V conflict-free.
__global__ __launch_bounds__(128, 2)
void attn_kernel(const float* __restrict__ v, float* __restrict__ out) {
    extern __shared__ float sm[];
    float* qs = sm + QOFF;
    float* ps = sm + POFF;

    const int bh  = blockIdx.y;
    const int qt  = (int)gridDim.x - 1 - (int)blockIdx.x;   // heavy-first
    const int b   = bh >> 4;
    const int q0  = qt * QT;
    const int tid = threadIdx.x;
    const int tx  = tid & 7;
    const int ty  = tid >> 3;            // 0..15

    const float* qr = g_qr + ((size_t)bh * SQ + q0) * DH;
    const float* kr = g_kr + (size_t)bh * SK * DH;
    const float* vp = v    + (size_t)bh * SK * DH;

    const int pmin = g_posq[b * SQ + q0];
    const int pmax = g_posq[b * SQ + q0 + QT - 1];
    const int nkt  = pmax / KTILE + 1;
    int p[4];
#pragma unroll
    for (int i = 0; i < 4; i++) p[i] = g_posq[b * SQ + q0 + ty + 16 * i];

    // cp.async loader: 1024 16B chunks K + 1024 V per tile; 128 thr -> 8+8 each
    const unsigned int smbase = (unsigned int)__cvta_generic_to_shared(sm);
    const int cr = tid >> 1;             // row 0..63
    const int cc = (tid & 1) * 8;        // col chunk group (8 chunks of 4 floats)

    // issue tile 0 copies
    {
        unsigned int kb = smbase + KOFF * 4;
        unsigned int vb = smbase + VOFF * 4;
        const float* krow = kr + (size_t)cr * DH;
        const float* vrow = vp + (size_t)cr * DH;
#pragma unroll
        for (int u = 0; u < 8; u++) {
            int c = cc + u;              // 0..15
            cpa16(kb + (cr * LS + c * 4) * 4, krow + c * 4);
            unsigned int vdst = (c < 8)
                ? vb + (cr * VHS + c * 4) * 4
                : vb + (VHALF + cr * VHS + (c - 8) * 4) * 4;
            cpa16(vdst, vrow + c * 4);
        }
        asm volatile("cp.async.commit_group;");
    }

    // load Q tile (plain LDG/STS; covered by first sync)
#pragma unroll
    for (int i = 0; i < 8; i++) {
        int fid = tid + i * 128;
        int r = fid >> 4, c = (fid & 15) * 4;
        float4 f = *(const float4*)(qr + r * DH + c);
        *(float4*)(qs + r * LS + c) = f;
    }

    float m[4], l[4];
    ull o2[4][4];
#pragma unroll
    for (int i = 0; i < 4; i++) {
        m[i] = -1e30f; l[i] = 0.f;
#pragma unroll
        for (int j = 0; j < 4; j++) o2[i][j] = 0ULL;
    }

    const float* qrow[4];
#pragma unroll
    for (int i = 0; i < 4; i++) qrow[i] = qs + (ty + 16 * i) * LS;

    for (int t = 0; t < nkt; t++) {
        const int bsel = t & 1;
        const float* ks  = sm + KOFF + bsel * KBUF;
        const float* vsb = sm + VOFF + bsel * VBUF;
        const int k0 = t * KTILE;

        asm volatile("cp.async.wait_group 0;");
        __syncthreads();                 // tile t visible; prev PV/P-reads done

        // prefetch tile t+1 into the other buffers
        if (t + 1 < nkt) {
            const int k0n = (t + 1) * KTILE;
            unsigned int kb = smbase + (KOFF + ((t + 1) & 1) * KBUF) * 4;
            unsigned int vb = smbase + (VOFF + ((t + 1) & 1) * VBUF) * 4;
            const float* krow = kr + (size_t)(k0n + cr) * DH;
            const float* vrow = vp + (size_t)(k0n + cr) * DH;
#pragma unroll
            for (int u = 0; u < 8; u++) {
                int c = cc + u;
                cpa16(kb + (cr * LS + c * 4) * 4, krow + c * 4);
                unsigned int vdst = (c < 8)
                    ? vb + (cr * VHS + c * 4) * 4
                    : vb + (VHALF + cr * VHS + (c - 8) * 4) * 4;
                cpa16(vdst, vrow + c * 4);
            }
        }
        asm volatile("cp.async.commit_group;");

        // ---- S = Q K^T (packed over reduction dim) ----
        ull s2[4][8];
#pragma unroll
        for (int i = 0; i < 4; i++)
#pragma unroll
            for (int j = 0; j < 8; j++) s2[i][j] = 0ULL;

#pragma unroll
        for (int kk = 0; kk < DH; kk += 4) {
            ulonglong2 a4[4], b4[8];
#pragma unroll
            for (int i = 0; i < 4; i++)
                a4[i] = *(const ulonglong2*)(qrow[i] + kk);
#pragma unroll
            for (int j = 0; j < 8; j++)
                b4[j] = *(const ulonglong2*)(ks + (tx + 8 * j) * LS + kk);
#pragma unroll
            for (int i = 0; i < 4; i++)
#pragma unroll
                for (int j = 0; j < 8; j++) {
                    s2[i][j] = ffma2(a4[i].x, b4[j].x, s2[i][j]);
                    s2[i][j] = ffma2(a4[i].y, b4[j].y, s2[i][j]);
                }
        }

        float s[4][8];
#pragma unroll
        for (int i = 0; i < 4; i++)
#pragma unroll
            for (int j = 0; j < 8; j++) {
                float lo, hi; upk2(s2[i][j], lo, hi);
                s[i][j] = lo + hi;
            }

        // causal mask (boundary tiles only)
        if (k0 + KTILE - 1 > pmin) {
#pragma unroll
            for (int i = 0; i < 4; i++)
#pragma unroll
                for (int j = 0; j < 8; j++)
                    if (k0 + tx + 8 * j > p[i]) s[i][j] = -1e30f;
        }

        // online softmax
        float fac[4];
#pragma unroll
        for (int i = 0; i < 4; i++) {
            float mt = s[i][0];
#pragma unroll
            for (int j = 1; j < 8; j++) mt = fmaxf(mt, s[i][j]);
            mt = fmaxf(mt, __shfl_xor_sync(0xffffffffu, mt, 1));
            mt = fmaxf(mt, __shfl_xor_sync(0xffffffffu, mt, 2));
            mt = fmaxf(mt, __shfl_xor_sync(0xffffffffu, mt, 4));
            float mn = fmaxf(m[i], mt);
            fac[i] = __expf(m[i] - mn);
            m[i] = mn;
            float rs = 0.f;
#pragma unroll
            for (int j = 0; j < 8; j++) { s[i][j] = __expf(s[i][j] - mn); rs += s[i][j]; }
            rs += __shfl_xor_sync(0xffffffffu, rs, 1);
            rs += __shfl_xor_sync(0xffffffffu, rs, 2);
            rs += __shfl_xor_sync(0xffffffffu, rs, 4);
            l[i] = l[i] * fac[i] + rs;
            ull f2 = pk2(fac[i], fac[i]);
#pragma unroll
            for (int j = 0; j < 4; j++) o2[i][j] = fmul2(o2[i][j], f2);
        }

        // stage P (separate buffer; banks 8ty+tx conflict-free)
#pragma unroll
        for (int i = 0; i < 4; i++)
#pragma unroll
            for (int j = 0; j < 8; j++)
                ps[(ty + 16 * i) * PS + tx + 8 * j] = s[i][j];
        __syncthreads();

        // ---- O += P V (V in two conflict-free halves) ----
        const float* va = vsb + (tx < 4 ? tx * 8 : VHALF + (tx - 4) * 8);
#pragma unroll
        for (int kk = 0; kk < KTILE; kk += 4) {
            float4 pa4[4];
#pragma unroll
            for (int i = 0; i < 4; i++)
                pa4[i] = *(const float4*)(ps + (ty + 16 * i) * PS + kk);
#pragma unroll
            for (int u = 0; u < 4; u++) {
                const float* vr = va + (kk + u) * VHS;
                ulonglong2 vv = *(const ulonglong2*)(vr);
                ulonglong2 vw = *(const ulonglong2*)(vr + 4);
#pragma unroll
                for (int i = 0; i < 4; i++) {
                    float pv = ((const float*)&pa4[i])[u];
                    ull pr = pk2(pv, pv);
                    o2[i][0] = ffma2(pr, vv.x, o2[i][0]);
                    o2[i][1] = ffma2(pr, vv.y, o2[i][1]);
                    o2[i][2] = ffma2(pr, vw.x, o2[i][2]);
                    o2[i][3] = ffma2(pr, vw.y, o2[i][3]);
                }
            }
        }
    }

    // epilogue
#pragma unroll
    for (int i = 0; i < 4; i++) {
        float inv = 1.0f / l[i];
        ull iv = pk2(inv, inv);
        ulonglong2 w0, w1;
        w0.x = fmul2(o2[i][0], iv); w0.y = fmul2(o2[i][1], iv);
        w1.x = fmul2(o2[i][2], iv); w1.y = fmul2(o2[i][3], iv);
        float* orow = out + ((size_t)bh * SQ + q0 + ty + 16 * i) * DH + tx * 8;
        *(ulonglong2*)orow       = w0;
        *(ulonglong2*)(orow + 4) = w1;
    }
}

// ---------------- launch ------------------------------------------------------
extern "C" void kernel_launch(void* const* d_in, const int* in_sizes, int n_in,
                              void* d_out, int out_size) {
    const float* q = nullptr; const float* k = nullptr; const float* v = nullptr;
    const void* cand[2] = {nullptr, nullptr}; int nc = 0;
    for (int i = 0; i < n_in; i++) {
        long long sz = in_sizes[i];
        if (sz == 4194304) { q = (const float*)d_in[i]; }
        else if (sz == 8388608) { if (!k) k = (const float*)d_in[i]; else v = (const float*)d_in[i]; }
        else if (sz == 8192) { if (nc < 2) cand[nc++] = d_in[i]; }
    }
    if (nc == 1) cand[1] = cand[0];
    if (!q || !k || !v || nc == 0) {
        q = (const float*)d_in[0]; k = (const float*)d_in[1]; v = (const float*)d_in[2];
        cand[0] = d_in[4]; cand[1] = d_in[5];
    }
    float* out = (float*)d_out;

    build_idx_kernel<<<BATCH, 1024>>>(cand[0], cand[1]);
    build_tab_kernel<<<(SK * 16 + 255) / 256, 256>>>();
    rope_q_kernel<<<(BH * SQ * 32 + 255) / 256, 256>>>(q);
    rope_k_kernel<<<(BH * SK * 32 + 255) / 256, 256>>>(k);

    const int smem_bytes = SMWORDS * (int)sizeof(float);   // 107776
    cudaFuncSetAttribute(attn_kernel,
                         cudaFuncAttributeMaxDynamicSharedMemorySize, smem_bytes);
    dim3 grid(SQ / QT, BH);
    attn_kernel<<<grid, 128, smem_bytes>>>(v, out);
}

// round 9
// speedup vs baseline: 1.3687x; 1.0240x over previous
#include <cuda_runtime.h>
#include <math.h>

#define BATCH  2
#define NHEADS 16
#define BH     32
#define SQ     2048
#define SK     4096
#define DH     64
#define QT     64
#define KTILE  64
#define LS     68          // Q/K smem row stride (floats)
#define PS     72          // P smem row stride: banks 8ty+tx, conflict-free
#define VHS    36          // V half-row stride
#define QSCALE 0.1803368801111f   // 0.125 * log2(e)
// smem word offsets
#define QOFF   0
#define KOFF   4352                   // Q: 64*68
#define KBUF   4352                   // per K buffer
#define VOFF   (KOFF + 2*KBUF)        // 13056
#define VBUF   4640                   // two 64x36 halves + pad; half1 at +2308
#define VHALF  2308
#define POFF   (VOFF + 2*VBUF)        // 22336
#define SMWORDS (POFF + QT*PS)        // 26944 words = 107776 B

typedef unsigned long long ull;

__device__ __forceinline__ ull pk2(float lo, float hi) {
    ull r; asm("mov.b64 %0,{%1,%2};" : "=l"(r) : "f"(lo), "f"(hi)); return r;
}
__device__ __forceinline__ void upk2(ull v, float& lo, float& hi) {
    asm("mov.b64 {%0,%1},%2;" : "=f"(lo), "=f"(hi) : "l"(v));
}
__device__ __forceinline__ ull ffma2(ull a, ull b, ull c) {
    ull d; asm("fma.rn.f32x2 %0,%1,%2,%3;" : "=l"(d) : "l"(a), "l"(b), "l"(c)); return d;
}
__device__ __forceinline__ ull fmul2(ull a, ull b) {
    ull d; asm("mul.rn.f32x2 %0,%1,%2;" : "=l"(d) : "l"(a), "l"(b)); return d;
}
__device__ __forceinline__ void cpa16(unsigned int dst, const void* src) {
    asm volatile("cp.async.cg.shared.global [%0], [%1], 16;" :: "r"(dst), "l"(src));
}

// ---------------- scratch ----------------
__device__ int   g_posq[BATCH * SQ];
__device__ float g_cosT[SK * 16];
__device__ float g_sinT[SK * 16];
__device__ float g_qr[BH * SQ * DH];
__device__ float g_kr[BH * SK * DH];

// ---------------- kernel 1: gather query positions -------------------------
__global__ void build_idx_kernel(const void* candA, const void* candB) {
    __shared__ int warp_sums[32];
    const int b   = blockIdx.x;
    const int tid = threadIdx.x;          // 1024 threads

    const int*   ai = (const int*)candA;  const float* af = (const float*)candA;
    const int*   bi = (const int*)candB;  const float* bf = (const float*)candB;
    bool a_is_pos = (ai[1] == 1 && ai[2] == 2 && ai[3] == 3 && ai[100] == 100) ||
                    (af[1] == 1.0f && af[2] == 2.0f && af[3] == 3.0f && af[100] == 100.0f);
    bool b_is_pos = (bi[1] == 1 && bi[2] == 2 && bi[3] == 3 && bi[100] == 100) ||
                    (bf[1] == 1.0f && bf[2] == 2.0f && bf[3] == 3.0f && bf[100] == 100.0f);
    const void* skipv = a_is_pos ? candB : (b_is_pos ? candA : candB);

    const unsigned int* sw = (const unsigned int*)skipv;
    bool w4 = true;
#pragma unroll
    for (int i = 0; i < 32; i++) {
        unsigned int x = sw[i];
        w4 = w4 && (x <= 1u || x == 0x3f800000u);
    }
    const unsigned char* s8  = (const unsigned char*)skipv;
    const unsigned int*  s32 = (const unsigned int*)skipv;

    g_posq[b * SQ + tid * 2]     = 0;
    g_posq[b * SQ + tid * 2 + 1] = 0;
    __syncthreads();

    const int base = tid * 4;
    int flags[4]; int c = 0;
#pragma unroll
    for (int u = 0; u < 4; u++) {
        int idx = b * SK + base + u;
        flags[u] = (w4 ? (s32[idx] != 0u) : (s8[idx] != 0)) ? 1 : 0;
        c += flags[u];
    }
    const int lane = tid & 31, warp = tid >> 5;
    int pre = c;
#pragma unroll
    for (int o = 1; o < 32; o <<= 1) {
        int t = __shfl_up_sync(0xffffffffu, pre, o);
        if (lane >= o) pre += t;
    }
    if (lane == 31) warp_sums[warp] = pre;
    __syncthreads();
    if (warp == 0) {
        int s = warp_sums[lane];
#pragma unroll
        for (int o = 1; o < 32; o <<= 1) {
            int t = __shfl_up_sync(0xffffffffu, s, o);
            if (lane >= o) s += t;
        }
        warp_sums[lane] = s;
    }
    __syncthreads();
    int offset = pre - c + (warp ? warp_sums[warp - 1] : 0);
#pragma unroll
    for (int u = 0; u < 4; u++) {
        if (flags[u] && offset < SQ)
            g_posq[b * SQ + offset] = base + u;
        offset += flags[u];
    }
}

// ---------------- kernel 2: cos/sin table ----------------------------------
__global__ void build_tab_kernel() {
    int i = blockIdx.x * blockDim.x + threadIdx.x;
    if (i >= SK * 16) return;
    int p = i >> 4, f = i & 15;
    float invf = (float)(1.0 / pow(10000.0, (double)(2 * f) / 32.0));
    float ang  = (float)p * invf;
    g_cosT[i] = cosf(ang);
    g_sinT[i] = sinf(ang);
}

// ---------------- kernel 3: RoPE on Q (scaled by 1/sqrt(D) * log2e) ---------
__global__ void rope_q_kernel(const float* __restrict__ q) {
    int t = blockIdx.x * blockDim.x + threadIdx.x;
    if (t >= BH * SQ * 32) return;
    int u   = t & 31;
    int row = t >> 5;
    int b   = row / (NHEADS * SQ);
    int r   = row & (SQ - 1);
    const float* x = q    + (size_t)row * DH;
    float*       y = g_qr + (size_t)row * DH;
    const float sc = QSCALE;
    if (u < 16) {
        int pos = g_posq[b * SQ + r];
        pos = min(max(pos, 0), SK - 1);
        float c  = g_cosT[pos * 16 + u];
        float s2 = g_sinT[pos * 16 + u];
        float x1 = x[u], x2 = x[u + 16];
        y[u]      = (x1 * c - x2 * s2) * sc;
        y[u + 16] = (x2 * c + x1 * s2) * sc;
    } else {
        int d = u + 16;
        y[d]      = x[d] * sc;
        y[d + 16] = x[d + 16] * sc;
    }
}

// ---------------- kernel 4: RoPE on K ---------------------------------------
__global__ void rope_k_kernel(const float* __restrict__ k) {
    int t = blockIdx.x * blockDim.x + threadIdx.x;
    if (t >= BH * SK * 32) return;
    int u   = t & 31;
    int row = t >> 5;
    int r   = row & (SK - 1);
    const float* x = k    + (size_t)row * DH;
    float*       y = g_kr + (size_t)row * DH;
    if (u < 16) {
        float c  = g_cosT[r * 16 + u];
        float s2 = g_sinT[r * 16 + u];
        float x1 = x[u], x2 = x[u + 16];
        y[u]      = x1 * c - x2 * s2;
        y[u + 16] = x2 * c + x1 * s2;
    } else {
        int d = u + 16;
        y[d]      = x[d];
        y[d + 16] = x[d + 16];
    }
}

// ---------------- kernel 5: flash attention (softmax pipelined) -------------
// 128 threads, 64q x 64k tile, microtile 4q x 8k. Softmax of tile t-1 overlaps
// QK of tile t (independent chains in one basic block). 1 block sync per tile.
__global__ __launch_bounds__(128, 2)
void attn_kernel(const float* __restrict__ v, float* __restrict__ out) {
    extern __shared__ float sm[];
    float* qs = sm + QOFF;
    float* ps = sm + POFF;

    const int bh  = blockIdx.y;
    const int qt  = (int)gridDim.x - 1 - (int)blockIdx.x;   // heavy-first
    const int b   = bh >> 4;
    const int q0  = qt * QT;
    const int tid = threadIdx.x;
    const int tx  = tid & 7;
    const int ty  = tid >> 3;            // 0..15

    const float* qr = g_qr + ((size_t)bh * SQ + q0) * DH;
    const float* kr = g_kr + (size_t)bh * SK * DH;
    const float* vp = v    + (size_t)bh * SK * DH;

    const int pmin = g_posq[b * SQ + q0];
    const int pmax = g_posq[b * SQ + q0 + QT - 1];
    const int nkt  = pmax / KTILE + 1;
    int p[4];
#pragma unroll
    for (int i = 0; i < 4; i++) p[i] = g_posq[b * SQ + q0 + ty + 16 * i];

    const unsigned int smbase = (unsigned int)__cvta_generic_to_shared(sm);
    const int cr = tid >> 1;             // row 0..63
    const int cc = (tid & 1) * 8;        // 8 chunks of 4 floats

    // prefetch K(0)
    {
        unsigned int kb = smbase + KOFF * 4;
        const float* krow = kr + (size_t)cr * DH;
#pragma unroll
        for (int u = 0; u < 8; u++) {
            int c = cc + u;
            cpa16(kb + (cr * LS + c * 4) * 4, krow + c * 4);
        }
        asm volatile("cp.async.commit_group;");
    }

    // load Q tile
#pragma unroll
    for (int i = 0; i < 8; i++) {
        int fid = tid + i * 128;
        int r = fid >> 4, c = (fid & 15) * 4;
        float4 f = *(const float4*)(qr + r * DH + c);
        *(float4*)(qs + r * LS + c) = f;
    }

    float m[4], l[4], sp[4][8];
    ull o2[4][4];
#pragma unroll
    for (int i = 0; i < 4; i++) {
        m[i] = -1e30f; l[i] = 0.f;
#pragma unroll
        for (int j = 0; j < 4; j++) o2[i][j] = 0ULL;
    }

    const float* qrow[4];
#pragma unroll
    for (int i = 0; i < 4; i++) qrow[i] = qs + (ty + 16 * i) * LS;

    // helper lambdas via macros -------------------------------------------------
#define ISSUE_K(T)                                                             \
    {                                                                          \
        unsigned int kb = smbase + (KOFF + ((T) & 1) * KBUF) * 4;              \
        const float* krow = kr + (size_t)((T) * KTILE + cr) * DH;              \
        _Pragma("unroll")                                                      \
        for (int u = 0; u < 8; u++) {                                          \
            int c = cc + u;                                                    \
            cpa16(kb + (cr * LS + c * 4) * 4, krow + c * 4);                   \
        }                                                                      \
    }
#define ISSUE_V(T)                                                             \
    {                                                                          \
        unsigned int vb = smbase + (VOFF + ((T) & 1) * VBUF) * 4;              \
        const float* vrow = vp + (size_t)((T) * KTILE + cr) * DH;              \
        _Pragma("unroll")                                                      \
        for (int u = 0; u < 8; u++) {                                          \
            int c = cc + u;                                                    \
            unsigned int vdst = (c < 8)                                        \
                ? vb + (cr * VHS + c * 4) * 4                                  \
                : vb + (VHALF + cr * VHS + (c - 8) * 4) * 4;                   \
            cpa16(vdst, vrow + c * 4);                                         \
        }                                                                      \
    }

#define QK_HALF(KS, KB)                                                        \
    _Pragma("unroll")                                                          \
    for (int kk = (KB); kk < (KB) + 32; kk += 4) {                             \
        ulonglong2 a4[4], b4[8];                                               \
        _Pragma("unroll")                                                      \
        for (int i = 0; i < 4; i++)                                            \
            a4[i] = *(const ulonglong2*)(qrow[i] + kk);                        \
        _Pragma("unroll")                                                      \
        for (int j = 0; j < 8; j++)                                            \
            b4[j] = *(const ulonglong2*)((KS) + (tx + 8 * j) * LS + kk);       \
        _Pragma("unroll")                                                      \
        for (int i = 0; i < 4; i++)                                            \
            _Pragma("unroll")                                                  \
            for (int j = 0; j < 8; j++) {                                      \
                s2[i][j] = ffma2(a4[i].x, b4[j].x, s2[i][j]);                  \
                s2[i][j] = ffma2(a4[i].y, b4[j].y, s2[i][j]);                  \
            }                                                                  \
    }

#define SOFTMAX_PSTORE()                                                       \
    {                                                                          \
        float fac[4];                                                          \
        _Pragma("unroll")                                                      \
        for (int i = 0; i < 4; i++) {                                          \
            float mt = sp[i][0];                                               \
            _Pragma("unroll")                                                  \
            for (int j = 1; j < 8; j++) mt = fmaxf(mt, sp[i][j]);              \
            mt = fmaxf(mt, __shfl_xor_sync(0xffffffffu, mt, 1));               \
            mt = fmaxf(mt, __shfl_xor_sync(0xffffffffu, mt, 2));               \
            mt = fmaxf(mt, __shfl_xor_sync(0xffffffffu, mt, 4));               \
            float mn = fmaxf(m[i], mt);                                        \
            fac[i] = exp2f(m[i] - mn);                                         \
            m[i] = mn;                                                         \
            float rs = 0.f;                                                    \
            _Pragma("unroll")                                                  \
            for (int j = 0; j < 8; j++) {                                      \
                sp[i][j] = exp2f(sp[i][j] - mn);                               \
                rs += sp[i][j];                                                \
            }                                                                  \
            rs += __shfl_xor_sync(0xffffffffu, rs, 1);                         \
            rs += __shfl_xor_sync(0xffffffffu, rs, 2);                         \
            rs += __shfl_xor_sync(0xffffffffu, rs, 4);                         \
            l[i] = l[i] * fac[i] + rs;                                         \
            ull f2 = pk2(fac[i], fac[i]);                                      \
            _Pragma("unroll")                                                  \
            for (int j = 0; j < 4; j++) o2[i][j] = fmul2(o2[i][j], f2);        \
        }                                                                      \
        _Pragma("unroll")                                                      \
        for (int i = 0; i < 4; i++)                                            \
            _Pragma("unroll")                                                  \
            for (int j = 0; j < 8; j++)                                        \
                ps[(ty + 16 * i) * PS + tx + 8 * j] = sp[i][j];                \
    }

#define PV_ACC(VSB)                                                            \
    {                                                                          \
        const float* va = (VSB) + (tx < 4 ? tx * 8 : VHALF + (tx - 4) * 8);    \
        _Pragma("unroll")                                                      \
        for (int kk = 0; kk < KTILE; kk += 4) {                                \
            float4 pa4[4];                                                     \
            _Pragma("unroll")                                                  \
            for (int i = 0; i < 4; i++)                                        \
                pa4[i] = *(const float4*)(ps + (ty + 16 * i) * PS + kk);       \
            _Pragma("unroll")                                                  \
            for (int u = 0; u < 4; u++) {                                      \
                const float* vr = va + (kk + u) * VHS;                         \
                ulonglong2 vv = *(const ulonglong2*)(vr);                      \
                ulonglong2 vw = *(const ulonglong2*)(vr + 4);                  \
                _Pragma("unroll")                                              \
                for (int i = 0; i < 4; i++) {                                  \
                    float pvv = ((const float*)&pa4[i])[u];                    \
                    ull pr = pk2(pvv, pvv);                                    \
                    o2[i][0] = ffma2(pr, vv.x, o2[i][0]);                      \
                    o2[i][1] = ffma2(pr, vv.y, o2[i][1]);                      \
                    o2[i][2] = ffma2(pr, vw.x, o2[i][2]);                      \
                    o2[i][3] = ffma2(pr, vw.y, o2[i][3]);                      \
                }                                                              \
            }                                                                  \
        }                                                                      \
    }

#define FOLD_MASK(K0)                                                          \
    {                                                                          \
        _Pragma("unroll")                                                      \
        for (int i = 0; i < 4; i++)                                            \
            _Pragma("unroll")                                                  \
            for (int j = 0; j < 8; j++) {                                      \
                float lo, hi; upk2(s2[i][j], lo, hi);                          \
                sp[i][j] = lo + hi;                                            \
            }                                                                  \
        if ((K0) + KTILE - 1 > pmin) {                                         \
            _Pragma("unroll")                                                  \
            for (int i = 0; i < 4; i++)                                        \
                _Pragma("unroll")                                              \
                for (int j = 0; j < 8; j++)                                    \
                    if ((K0) + tx + 8 * j > p[i]) sp[i][j] = -1e30f;           \
        }                                                                      \
    }

    // ---- peel t = 0 : QK only ----
    {
        asm volatile("cp.async.wait_group 0;");
        __syncthreads();
        if (1 < nkt) ISSUE_K(1);
        ISSUE_V(0);
        asm volatile("cp.async.commit_group;");

        ull s2[4][8];
#pragma unroll
        for (int i = 0; i < 4; i++)
#pragma unroll
            for (int j = 0; j < 8; j++) s2[i][j] = 0ULL;
        const float* ks = sm + KOFF;
        QK_HALF(ks, 0);
        QK_HALF(ks, 32);
        FOLD_MASK(0);
    }

    // ---- main pipelined loop ----
    for (int t = 1; t < nkt; t++) {
        const float* ks    = sm + KOFF + (t & 1) * KBUF;
        const float* vprev = sm + VOFF + ((t - 1) & 1) * VBUF;

        asm volatile("cp.async.wait_group 0;");
        __syncthreads();
        if (t + 1 < nkt) ISSUE_K(t + 1);
        ISSUE_V(t);
        asm volatile("cp.async.commit_group;");

        ull s2[4][8];
#pragma unroll
        for (int i = 0; i < 4; i++)
#pragma unroll
            for (int j = 0; j < 8; j++) s2[i][j] = 0ULL;

        // QK part 1 + softmax(t-1): independent chains, same basic block
        QK_HALF(ks, 0);
        SOFTMAX_PSTORE();
        __syncwarp();
        QK_HALF(ks, 32);
        PV_ACC(vprev);
        FOLD_MASK(t * KTILE);
    }

    // ---- tail: softmax + PV of last tile ----
    asm volatile("cp.async.wait_group 0;");
    __syncthreads();
    SOFTMAX_PSTORE();
    __syncwarp();
    {
        const float* vlast = sm + VOFF + ((nkt - 1) & 1) * VBUF;
        PV_ACC(vlast);
    }

    // epilogue
#pragma unroll
    for (int i = 0; i < 4; i++) {
        float inv = 1.0f / l[i];
        ull iv = pk2(inv, inv);
        ulonglong2 w0, w1;
        w0.x = fmul2(o2[i][0], iv); w0.y = fmul2(o2[i][1], iv);
        w1.x = fmul2(o2[i][2], iv); w1.y = fmul2(o2[i][3], iv);
        float* orow = out + ((size_t)bh * SQ + q0 + ty + 16 * i) * DH + tx * 8;
        *(ulonglong2*)orow       = w0;
        *(ulonglong2*)(orow + 4) = w1;
    }
}

// ---------------- launch ------------------------------------------------------
extern "C" void kernel_launch(void* const* d_in, const int* in_sizes, int n_in,
                              void* d_out, int out_size) {
    const float* q = nullptr; const float* k = nullptr; const float* v = nullptr;
    const void* cand[2] = {nullptr, nullptr}; int nc = 0;
    for (int i = 0; i < n_in; i++) {
        long long sz = in_sizes[i];
        if (sz == 4194304) { q = (const float*)d_in[i]; }
        else if (sz == 8388608) { if (!k) k = (const float*)d_in[i]; else v = (const float*)d_in[i]; }
        else if (sz == 8192) { if (nc < 2) cand[nc++] = d_in[i]; }
    }
    if (nc == 1) cand[1] = cand[0];
    if (!q || !k || !v || nc == 0) {
        q = (const float*)d_in[0]; k = (const float*)d_in[1]; v = (const float*)d_in[2];
        cand[0] = d_in[4]; cand[1] = d_in[5];
    }
    float* out = (float*)d_out;

    build_idx_kernel<<<BATCH, 1024>>>(cand[0], cand[1]);
    build_tab_kernel<<<(SK * 16 + 255) / 256, 256>>>();
    rope_q_kernel<<<(BH * SQ * 32 + 255) / 256, 256>>>(q);
    rope_k_kernel<<<(BH * SK * 32 + 255) / 256, 256>>>(k);

    const int smem_bytes = SMWORDS * (int)sizeof(float);   // 107776
    cudaFuncSetAttribute(attn_kernel,
                         cudaFuncAttributeMaxDynamicSharedMemorySize, smem_bytes);
    dim3 grid(SQ / QT, BH);
    attn_kernel<<<grid, 128, smem_bytes>>>(v, out);
}

// round 10
// speedup vs baseline: 1.3691x; 1.0003x over previous
#include <cuda_runtime.h>
#include <math.h>

#define BATCH  2
#define NHEADS 16
#define BH     32
#define SQ     2048
#define SK     4096
#define DH     64
#define QT     64
#define KTILE  64
#define LS     68          // Q/K smem row stride (floats)
#define PS     72          // P smem row stride: banks 8ty+tx, conflict-free
#define VHS    36          // V half-row stride
#define QSCALE 0.1803368801111f   // 0.125 * log2(e)
// smem word offsets
#define QOFF   0
#define KOFF   4352                   // Q: 64*68
#define KBUF   4352                   // per K buffer
#define VOFF   (KOFF + 2*KBUF)        // 13056
#define VBUF   4640                   // two 64x36 halves + pad; half1 at +2308
#define VHALF  2308
#define POFF   (VOFF + 2*VBUF)        // 22336
#define SMWORDS (POFF + QT*PS)        // 26944 words = 107776 B

typedef unsigned long long ull;

__device__ __forceinline__ ull pk2(float lo, float hi) {
    ull r; asm("mov.b64 %0,{%1,%2};" : "=l"(r) : "f"(lo), "f"(hi)); return r;
}
__device__ __forceinline__ void upk2(ull v, float& lo, float& hi) {
    asm("mov.b64 {%0,%1},%2;" : "=f"(lo), "=f"(hi) : "l"(v));
}
__device__ __forceinline__ ull ffma2(ull a, ull b, ull c) {
    ull d; asm("fma.rn.f32x2 %0,%1,%2,%3;" : "=l"(d) : "l"(a), "l"(b), "l"(c)); return d;
}
__device__ __forceinline__ ull fmul2(ull a, ull b) {
    ull d; asm("mul.rn.f32x2 %0,%1,%2;" : "=l"(d) : "l"(a), "l"(b)); return d;
}
__device__ __forceinline__ void cpa16(unsigned int dst, const void* src) {
    asm volatile("cp.async.cg.shared.global [%0], [%1], 16;" :: "r"(dst), "l"(src));
}

// ---------------- scratch ----------------
__device__ int   g_posq[BATCH * SQ];
__device__ float g_cosT[SK * 16];
__device__ float g_sinT[SK * 16];
__device__ float g_qr[BH * SQ * DH];
__device__ float g_kr[BH * SK * DH];

// ---------------- kernel 1: gather query positions -------------------------
__global__ void build_idx_kernel(const void* candA, const void* candB) {
    __shared__ int warp_sums[32];
    const int b   = blockIdx.x;
    const int tid = threadIdx.x;          // 1024 threads

    const int*   ai = (const int*)candA;  const float* af = (const float*)candA;
    const int*   bi = (const int*)candB;  const float* bf = (const float*)candB;
    bool a_is_pos = (ai[1] == 1 && ai[2] == 2 && ai[3] == 3 && ai[100] == 100) ||
                    (af[1] == 1.0f && af[2] == 2.0f && af[3] == 3.0f && af[100] == 100.0f);
    bool b_is_pos = (bi[1] == 1 && bi[2] == 2 && bi[3] == 3 && bi[100] == 100) ||
                    (bf[1] == 1.0f && bf[2] == 2.0f && bf[3] == 3.0f && bf[100] == 100.0f);
    const void* skipv = a_is_pos ? candB : (b_is_pos ? candA : candB);

    const unsigned int* sw = (const unsigned int*)skipv;
    bool w4 = true;
#pragma unroll
    for (int i = 0; i < 32; i++) {
        unsigned int x = sw[i];
        w4 = w4 && (x <= 1u || x == 0x3f800000u);
    }
    const unsigned char* s8  = (const unsigned char*)skipv;
    const unsigned int*  s32 = (const unsigned int*)skipv;

    g_posq[b * SQ + tid * 2]     = 0;
    g_posq[b * SQ + tid * 2 + 1] = 0;
    __syncthreads();

    const int base = tid * 4;
    int flags[4]; int c = 0;
#pragma unroll
    for (int u = 0; u < 4; u++) {
        int idx = b * SK + base + u;
        flags[u] = (w4 ? (s32[idx] != 0u) : (s8[idx] != 0)) ? 1 : 0;
        c += flags[u];
    }
    const int lane = tid & 31, warp = tid >> 5;
    int pre = c;
#pragma unroll
    for (int o = 1; o < 32; o <<= 1) {
        int t = __shfl_up_sync(0xffffffffu, pre, o);
        if (lane >= o) pre += t;
    }
    if (lane == 31) warp_sums[warp] = pre;
    __syncthreads();
    if (warp == 0) {
        int s = warp_sums[lane];
#pragma unroll
        for (int o = 1; o < 32; o <<= 1) {
            int t = __shfl_up_sync(0xffffffffu, s, o);
            if (lane >= o) s += t;
        }
        warp_sums[lane] = s;
    }
    __syncthreads();
    int offset = pre - c + (warp ? warp_sums[warp - 1] : 0);
#pragma unroll
    for (int u = 0; u < 4; u++) {
        if (flags[u] && offset < SQ)
            g_posq[b * SQ + offset] = base + u;
        offset += flags[u];
    }
}

// ---------------- kernel 2: cos/sin table ----------------------------------
__global__ void build_tab_kernel() {
    int i = blockIdx.x * blockDim.x + threadIdx.x;
    if (i >= SK * 16) return;
    int p = i >> 4, f = i & 15;
    float invf = (float)(1.0 / pow(10000.0, (double)(2 * f) / 32.0));
    float ang  = (float)p * invf;
    g_cosT[i] = cosf(ang);
    g_sinT[i] = sinf(ang);
}

// ---------------- kernel 3: RoPE on Q (scaled by 1/sqrt(D) * log2e) ---------
__global__ void rope_q_kernel(const float* __restrict__ q) {
    int t = blockIdx.x * blockDim.x + threadIdx.x;
    if (t >= BH * SQ * 32) return;
    int u   = t & 31;
    int row = t >> 5;
    int b   = row / (NHEADS * SQ);
    int r   = row & (SQ - 1);
    const float* x = q    + (size_t)row * DH;
    float*       y = g_qr + (size_t)row * DH;
    const float sc = QSCALE;
    if (u < 16) {
        int pos = g_posq[b * SQ + r];
        pos = min(max(pos, 0), SK - 1);
        float c  = g_cosT[pos * 16 + u];
        float s2 = g_sinT[pos * 16 + u];
        float x1 = x[u], x2 = x[u + 16];
        y[u]      = (x1 * c - x2 * s2) * sc;
        y[u + 16] = (x2 * c + x1 * s2) * sc;
    } else {
        int d = u + 16;
        y[d]      = x[d] * sc;
        y[d + 16] = x[d + 16] * sc;
    }
}

// ---------------- kernel 4: RoPE on K ---------------------------------------
__global__ void rope_k_kernel(const float* __restrict__ k) {
    int t = blockIdx.x * blockDim.x + threadIdx.x;
    if (t >= BH * SK * 32) return;
    int u   = t & 31;
    int row = t >> 5;
    int r   = row & (SK - 1);
    const float* x = k    + (size_t)row * DH;
    float*       y = g_kr + (size_t)row * DH;
    if (u < 16) {
        float c  = g_cosT[r * 16 + u];
        float s2 = g_sinT[r * 16 + u];
        float x1 = x[u], x2 = x[u + 16];
        y[u]      = x1 * c - x2 * s2;
        y[u + 16] = x2 * c + x1 * s2;
    } else {
        int d = u + 16;
        y[d]      = x[d];
        y[d + 16] = x[d + 16];
    }
}

// ---------------- kernel 5: flash attention (softmax pipelined) -------------
// 128 threads, 64q x 64k tile, microtile 4q x 8k. Softmax of tile t-1 overlaps
// QK of tile t (independent chains in one basic block). 1 block sync per tile.
__global__ __launch_bounds__(128, 2)
void attn_kernel(const float* __restrict__ v, float* __restrict__ out) {
    extern __shared__ float sm[];
    float* qs = sm + QOFF;
    float* ps = sm + POFF;

    const int bh  = blockIdx.y;
    const int qt  = (int)gridDim.x - 1 - (int)blockIdx.x;   // heavy-first
    const int b   = bh >> 4;
    const int q0  = qt * QT;
    const int tid = threadIdx.x;
    const int tx  = tid & 7;
    const int ty  = tid >> 3;            // 0..15

    const float* qr = g_qr + ((size_t)bh * SQ + q0) * DH;
    const float* kr = g_kr + (size_t)bh * SK * DH;
    const float* vp = v    + (size_t)bh * SK * DH;

    const int pmin = g_posq[b * SQ + q0];
    const int pmax = g_posq[b * SQ + q0 + QT - 1];
    const int nkt  = pmax / KTILE + 1;
    int p[4];
#pragma unroll
    for (int i = 0; i < 4; i++) p[i] = g_posq[b * SQ + q0 + ty + 16 * i];

    const unsigned int smbase = (unsigned int)__cvta_generic_to_shared(sm);
    const int cr = tid >> 1;             // row 0..63
    const int cc = (tid & 1) * 8;        // 8 chunks of 4 floats

    // prefetch K(0)
    {
        unsigned int kb = smbase + KOFF * 4;
        const float* krow = kr + (size_t)cr * DH;
#pragma unroll
        for (int u = 0; u < 8; u++) {
            int c = cc + u;
            cpa16(kb + (cr * LS + c * 4) * 4, krow + c * 4);
        }
        asm volatile("cp.async.commit_group;");
    }

    // load Q tile
#pragma unroll
    for (int i = 0; i < 8; i++) {
        int fid = tid + i * 128;
        int r = fid >> 4, c = (fid & 15) * 4;
        float4 f = *(const float4*)(qr + r * DH + c);
        *(float4*)(qs + r * LS + c) = f;
    }

    float m[4], l[4], sp[4][8];
    ull o2[4][4];
#pragma unroll
    for (int i = 0; i < 4; i++) {
        m[i] = -1e30f; l[i] = 0.f;
#pragma unroll
        for (int j = 0; j < 4; j++) o2[i][j] = 0ULL;
    }

    const float* qrow[4];
#pragma unroll
    for (int i = 0; i < 4; i++) qrow[i] = qs + (ty + 16 * i) * LS;

    // helper lambdas via macros -------------------------------------------------
#define ISSUE_K(T)                                                             \
    {                                                                          \
        unsigned int kb = smbase + (KOFF + ((T) & 1) * KBUF) * 4;              \
        const float* krow = kr + (size_t)((T) * KTILE + cr) * DH;              \
        _Pragma("unroll")                                                      \
        for (int u = 0; u < 8; u++) {                                          \
            int c = cc + u;                                                    \
            cpa16(kb + (cr * LS + c * 4) * 4, krow + c * 4);                   \
        }                                                                      \
    }
#define ISSUE_V(T)                                                             \
    {                                                                          \
        unsigned int vb = smbase + (VOFF + ((T) & 1) * VBUF) * 4;              \
        const float* vrow = vp + (size_t)((T) * KTILE + cr) * DH;              \
        _Pragma("unroll")                                                      \
        for (int u = 0; u < 8; u++) {                                          \
            int c = cc + u;                                                    \
            unsigned int vdst = (c < 8)                                        \
                ? vb + (cr * VHS + c * 4) * 4                                  \
                : vb + (VHALF + cr * VHS + (c - 8) * 4) * 4;                   \
            cpa16(vdst, vrow + c * 4);                                         \
        }                                                                      \
    }

#define QK_HALF(KS, KB)                                                        \
    _Pragma("unroll")                                                          \
    for (int kk = (KB); kk < (KB) + 32; kk += 4) {                             \
        ulonglong2 a4[4], b4[8];                                               \
        _Pragma("unroll")                                                      \
        for (int i = 0; i < 4; i++)                                            \
            a4[i] = *(const ulonglong2*)(qrow[i] + kk);                        \
        _Pragma("unroll")                                                      \
        for (int j = 0; j < 8; j++)                                            \
            b4[j] = *(const ulonglong2*)((KS) + (tx + 8 * j) * LS + kk);       \
        _Pragma("unroll")                                                      \
        for (int i = 0; i < 4; i++)                                            \
            _Pragma("unroll")                                                  \
            for (int j = 0; j < 8; j++) {                                      \
                s2[i][j] = ffma2(a4[i].x, b4[j].x, s2[i][j]);                  \
                s2[i][j] = ffma2(a4[i].y, b4[j].y, s2[i][j]);                  \
            }                                                                  \
    }

#define SOFTMAX_PSTORE()                                                       \
    {                                                                          \
        float fac[4];                                                          \
        _Pragma("unroll")                                                      \
        for (int i = 0; i < 4; i++) {                                          \
            float mt = sp[i][0];                                               \
            _Pragma("unroll")                                                  \
            for (int j = 1; j < 8; j++) mt = fmaxf(mt, sp[i][j]);              \
            mt = fmaxf(mt, __shfl_xor_sync(0xffffffffu, mt, 1));               \
            mt = fmaxf(mt, __shfl_xor_sync(0xffffffffu, mt, 2));               \
            mt = fmaxf(mt, __shfl_xor_sync(0xffffffffu, mt, 4));               \
            float mn = fmaxf(m[i], mt);                                        \
            fac[i] = exp2f(m[i] - mn);                                         \
            m[i] = mn;                                                         \
            float rs = 0.f;                                                    \
            _Pragma("unroll")                                                  \
            for (int j = 0; j < 8; j++) {                                      \
                sp[i][j] = exp2f(sp[i][j] - mn);                               \
                rs += sp[i][j];                                                \
            }                                                                  \
            rs += __shfl_xor_sync(0xffffffffu, rs, 1);                         \
            rs += __shfl_xor_sync(0xffffffffu, rs, 2);                         \
            rs += __shfl_xor_sync(0xffffffffu, rs, 4);                         \
            l[i] = l[i] * fac[i] + rs;                                         \
            ull f2 = pk2(fac[i], fac[i]);                                      \
            _Pragma("unroll")                                                  \
            for (int j = 0; j < 4; j++) o2[i][j] = fmul2(o2[i][j], f2);        \
        }                                                                      \
        _Pragma("unroll")                                                      \
        for (int i = 0; i < 4; i++)                                            \
            _Pragma("unroll")                                                  \
            for (int j = 0; j < 8; j++)                                        \
                ps[(ty + 16 * i) * PS + tx + 8 * j] = sp[i][j];                \
    }

#define PV_ACC(VSB)                                                            \
    {                                                                          \
        const float* va = (VSB) + (tx < 4 ? tx * 8 : VHALF + (tx - 4) * 8);    \
        _Pragma("unroll")                                                      \
        for (int kk = 0; kk < KTILE; kk += 4) {                                \
            float4 pa4[4];                                                     \
            _Pragma("unroll")                                                  \
            for (int i = 0; i < 4; i++)                                        \
                pa4[i] = *(const float4*)(ps + (ty + 16 * i) * PS + kk);       \
            _Pragma("unroll")                                                  \
            for (int u = 0; u < 4; u++) {                                      \
                const float* vr = va + (kk + u) * VHS;                         \
                ulonglong2 vv = *(const ulonglong2*)(vr);                      \
                ulonglong2 vw = *(const ulonglong2*)(vr + 4);                  \
                _Pragma("unroll")                                              \
                for (int i = 0; i < 4; i++) {                                  \
                    float pvv = ((const float*)&pa4[i])[u];                    \
                    ull pr = pk2(pvv, pvv);                                    \
                    o2[i][0] = ffma2(pr, vv.x, o2[i][0]);                      \
                    o2[i][1] = ffma2(pr, vv.y, o2[i][1]);                      \
                    o2[i][2] = ffma2(pr, vw.x, o2[i][2]);                      \
                    o2[i][3] = ffma2(pr, vw.y, o2[i][3]);                      \
                }                                                              \
            }                                                                  \
        }                                                                      \
    }

#define FOLD_MASK(K0)                                                          \
    {                                                                          \
        _Pragma("unroll")                                                      \
        for (int i = 0; i < 4; i++)                                            \
            _Pragma("unroll")                                                  \
            for (int j = 0; j < 8; j++) {                                      \
                float lo, hi; upk2(s2[i][j], lo, hi);                          \
                sp[i][j] = lo + hi;                                            \
            }                                                                  \
        if ((K0) + KTILE - 1 > pmin) {                                         \
            _Pragma("unroll")                                                  \
            for (int i = 0; i < 4; i++)                                        \
                _Pragma("unroll")                                              \
                for (int j = 0; j < 8; j++)                                    \
                    if ((K0) + tx + 8 * j > p[i]) sp[i][j] = -1e30f;           \
        }                                                                      \
    }

    // ---- peel t = 0 : QK only ----
    {
        asm volatile("cp.async.wait_group 0;");
        __syncthreads();
        if (1 < nkt) ISSUE_K(1);
        ISSUE_V(0);
        asm volatile("cp.async.commit_group;");

        ull s2[4][8];
#pragma unroll
        for (int i = 0; i < 4; i++)
#pragma unroll
            for (int j = 0; j < 8; j++) s2[i][j] = 0ULL;
        const float* ks = sm + KOFF;
        QK_HALF(ks, 0);
        QK_HALF(ks, 32);
        FOLD_MASK(0);
    }

    // ---- main pipelined loop ----
    for (int t = 1; t < nkt; t++) {
        const float* ks    = sm + KOFF + (t & 1) * KBUF;
        const float* vprev = sm + VOFF + ((t - 1) & 1) * VBUF;

        asm volatile("cp.async.wait_group 0;");
        __syncthreads();
        if (t + 1 < nkt) ISSUE_K(t + 1);
        ISSUE_V(t);
        asm volatile("cp.async.commit_group;");

        ull s2[4][8];
#pragma unroll
        for (int i = 0; i < 4; i++)
#pragma unroll
            for (int j = 0; j < 8; j++) s2[i][j] = 0ULL;

        // QK part 1 + softmax(t-1): independent chains, same basic block
        QK_HALF(ks, 0);
        SOFTMAX_PSTORE();
        __syncwarp();
        QK_HALF(ks, 32);
        PV_ACC(vprev);
        FOLD_MASK(t * KTILE);
    }

    // ---- tail: softmax + PV of last tile ----
    asm volatile("cp.async.wait_group 0;");
    __syncthreads();
    SOFTMAX_PSTORE();
    __syncwarp();
    {
        const float* vlast = sm + VOFF + ((nkt - 1) & 1) * VBUF;
        PV_ACC(vlast);
    }

    // epilogue
#pragma unroll
    for (int i = 0; i < 4; i++) {
        float inv = 1.0f / l[i];
        ull iv = pk2(inv, inv);
        ulonglong2 w0, w1;
        w0.x = fmul2(o2[i][0], iv); w0.y = fmul2(o2[i][1], iv);
        w1.x = fmul2(o2[i][2], iv); w1.y = fmul2(o2[i][3], iv);
        float* orow = out + ((size_t)bh * SQ + q0 + ty + 16 * i) * DH + tx * 8;
        *(ulonglong2*)orow       = w0;
        *(ulonglong2*)(orow + 4) = w1;
    }
}

// ---------------- launch ------------------------------------------------------
extern "C" void kernel_launch(void* const* d_in, const int* in_sizes, int n_in,
                              void* d_out, int out_size) {
    const float* q = nullptr; const float* k = nullptr; const float* v = nullptr;
    const void* cand[2] = {nullptr, nullptr}; int nc = 0;
    for (int i = 0; i < n_in; i++) {
        long long sz = in_sizes[i];
        if (sz == 4194304) { q = (const float*)d_in[i]; }
        else if (sz == 8388608) { if (!k) k = (const float*)d_in[i]; else v = (const float*)d_in[i]; }
        else if (sz == 8192) { if (nc < 2) cand[nc++] = d_in[i]; }
    }
    if (nc == 1) cand[1] = cand[0];
    if (!q || !k || !v || nc == 0) {
        q = (const float*)d_in[0]; k = (const float*)d_in[1]; v = (const float*)d_in[2];
        cand[0] = d_in[4]; cand[1] = d_in[5];
    }
    float* out = (float*)d_out;

    build_idx_kernel<<<BATCH, 1024>>>(cand[0], cand[1]);
    build_tab_kernel<<<(SK * 16 + 255) / 256, 256>>>();
    rope_q_kernel<<<(BH * SQ * 32 + 255) / 256, 256>>>(q);
    rope_k_kernel<<<(BH * SK * 32 + 255) / 256, 256>>>(k);

    const int smem_bytes = SMWORDS * (int)sizeof(float);   // 107776
    cudaFuncSetAttribute(attn_kernel,
                         cudaFuncAttributeMaxDynamicSharedMemorySize, smem_bytes);
    dim3 grid(SQ / QT, BH);
    attn_kernel<<<grid, 128, smem_bytes>>>(v, out);
}